// round 6
// baseline (speedup 1.0000x reference)
#include <cuda_runtime.h>
#include <cstdint>

// Derivation: layer_norm over the size-1 kv feature axis returns exactly
// ln_k_b (mu=x, var=0), so k and v are identical for every key position;
// softmax over identical scores is uniform; o = mean_l(v) = v for every query.
// Hence out = msa + row, row[c] = sum_d (ln_k_b*Wv[d] + bv[d])*Wo[d,c] + bo[c],
// broadcast over all 16384 rows. Exact identity, independent of input values.
__device__ float g_row[256];

// ---------------- Kernel 1: tiny GEMV for the broadcast row ----------------
__global__ void compute_row_kernel(const float* __restrict__ ln_k_b,
                                   const float* __restrict__ Wv,   // [1,256]
                                   const float* __restrict__ bv,   // [256]
                                   const float* __restrict__ Wo,   // [256,256]
                                   const float* __restrict__ bo)   // [256]
{
    __shared__ float4 part[256];
    int t = threadIdx.x;
    int c4 = blockIdx.x;               // channels 4*c4 .. 4*c4+3
    float kb = ln_k_b[0];
    float vd = fmaf(kb, Wv[t], bv[t]); // v[d=t]; kv_x == ln_k_b exactly

    float4 w = reinterpret_cast<const float4*>(Wo)[t * 64 + c4];
    float4 p;
    p.x = vd * w.x; p.y = vd * w.y; p.z = vd * w.z; p.w = vd * w.w;
    part[t] = p;
    __syncthreads();

    #pragma unroll
    for (int s = 128; s >= 1; s >>= 1) {
        if (t < s) {
            float4 a = part[t], b = part[t + s];
            a.x += b.x; a.y += b.y; a.z += b.z; a.w += b.w;
            part[t] = a;
        }
        __syncthreads();
    }
    if (t == 0) {
        float4 r = part[0];
        float4 b4 = reinterpret_cast<const float4*>(bo)[c4];
        r.x += b4.x; r.y += b4.y; r.z += b4.z; r.w += b4.w;
        reinterpret_cast<float4*>(g_row)[c4] = r;
    }
}

// ---------------- Kernel 2: TMA bulk-copy stream ----------------
// 512 blocks x 2 chunks x 16KB = 16.78MB exactly (n4 = 1,048,576 float4).
// Per block: both bulk loads issued up front; per chunk: wait -> add row in
// smem -> fence -> bulk store. No buffer reuse -> no mid-loop wait_group.

#define CHUNK_BYTES 16384
#define CHUNK_F4    1024

__device__ __forceinline__ uint32_t smem_u32(const void* p) {
    uint32_t a;
    asm("{ .reg .u64 t; cvta.to.shared.u64 t, %1; cvt.u32.u64 %0, t; }"
        : "=r"(a) : "l"(p));
    return a;
}

__global__ void __launch_bounds__(256)
add_row_tma_kernel(const float* __restrict__ msa,
                   float* __restrict__ out)
{
    __shared__ __align__(16) float4 buf[2][CHUNK_F4];       // 32 KB
    __shared__ __align__(8)  unsigned long long mbar[2];

    const int t = threadIdx.x;
    const long long blk_off = (long long)blockIdx.x * (2 * CHUNK_F4); // float4 units

    if (t == 0) {
        uint32_t mb0 = smem_u32(&mbar[0]);
        uint32_t mb1 = smem_u32(&mbar[1]);
        asm volatile("mbarrier.init.shared.b64 [%0], 1;" :: "r"(mb0) : "memory");
        asm volatile("mbarrier.init.shared.b64 [%0], 1;" :: "r"(mb1) : "memory");
        // make inits visible to the async proxy before TMA targets them
        asm volatile("fence.proxy.async.shared::cta;" ::: "memory");
        // issue both bulk loads immediately
        #pragma unroll
        for (int c = 0; c < 2; ++c) {
            uint32_t mb = smem_u32(&mbar[c]);
            uint32_t sd = smem_u32(&buf[c][0]);
            const void* gsrc = (const void*)(msa + (blk_off + c * CHUNK_F4) * 4);
            asm volatile(
                "mbarrier.arrive.expect_tx.shared.b64 _, [%0], %1;"
                :: "r"(mb), "r"((uint32_t)CHUNK_BYTES) : "memory");
            asm volatile(
                "cp.async.bulk.shared::cluster.global.mbarrier::complete_tx::bytes "
                "[%0], [%1], %2, [%3];"
                :: "r"(sd), "l"(gsrc), "r"((uint32_t)CHUNK_BYTES), "r"(mb)
                : "memory");
        }
    }
    __syncthreads();

    // broadcast row value for this thread (chunk stride 256 float4 -> t & 63)
    const float4 r = reinterpret_cast<const float4*>(g_row)[t & 63];

    #pragma unroll
    for (int c = 0; c < 2; ++c) {
        // all threads wait for chunk c arrival (parity 0, single-use barrier)
        {
            uint32_t mb = smem_u32(&mbar[c]);
            asm volatile(
                "{\n\t"
                ".reg .pred P;\n\t"
                "WAIT_%=:\n\t"
                "mbarrier.try_wait.parity.shared.b64 P, [%0], 0;\n\t"
                "@!P bra WAIT_%=;\n\t"
                "}"
                :: "r"(mb) : "memory");
        }
        // add broadcast row in-place: 4 float4 per thread
        #pragma unroll
        for (int k = 0; k < 4; ++k) {
            float4 m = buf[c][k * 256 + t];
            m.x += r.x; m.y += r.y; m.z += r.z; m.w += r.w;
            buf[c][k * 256 + t] = m;
        }
        __syncthreads();
        if (t == 0) {
            asm volatile("fence.proxy.async.shared::cta;" ::: "memory");
            uint32_t ss = smem_u32(&buf[c][0]);
            void* gdst = (void*)(out + (blk_off + c * CHUNK_F4) * 4);
            asm volatile(
                "cp.async.bulk.global.shared::cta.bulk_group [%0], [%1], %2;"
                :: "l"(gdst), "r"(ss), "r"((uint32_t)CHUNK_BYTES) : "memory");
            asm volatile("cp.async.bulk.commit_group;" ::: "memory");
        }
        // no __syncthreads needed: next chunk uses the other buffer/barrier
    }

    if (t == 0) {
        asm volatile("cp.async.bulk.wait_group 0;" ::: "memory");
    }
}

// Fallback (shape-general, used only if out_size isn't the expected 4M floats)
__global__ void add_row_fallback(const float4* __restrict__ msa4,
                                 float4* __restrict__ out4, int n4)
{
    int i = blockIdx.x * blockDim.x + threadIdx.x;
    if (i < n4) {
        float4 m = msa4[i];
        float4 r = reinterpret_cast<const float4*>(g_row)[i & 63];
        m.x += r.x; m.y += r.y; m.z += r.z; m.w += r.w;
        out4[i] = m;
    }
}

extern "C" void kernel_launch(void* const* d_in, const int* in_sizes, int n_in,
                              void* d_out, int out_size)
{
    // metadata order: 0 msa, 1 saxs, 2 ln_q_w, 3 ln_q_b, 4 ln_k_w, 5 ln_k_b,
    //                 6 Wq, 7 bq, 8 Wk, 9 bk, 10 Wv, 11 bv, 12 Wo, 13 bo
    const float* msa    = (const float*)d_in[0];
    const float* ln_k_b = (const float*)d_in[5];
    const float* Wv     = (const float*)d_in[10];
    const float* bv     = (const float*)d_in[11];
    const float* Wo     = (const float*)d_in[12];
    const float* bo     = (const float*)d_in[13];
    float* out = (float*)d_out;

    compute_row_kernel<<<64, 256>>>(ln_k_b, Wv, bv, Wo, bo);

    if (out_size == 512 * 2 * CHUNK_F4 * 4) {
        add_row_tma_kernel<<<512, 256>>>(msa, out);
    } else {
        int n4 = out_size / 4;
        add_row_fallback<<<(n4 + 255) / 256, 256>>>(
            (const float4*)msa, (float4*)out, n4);
    }
}